// round 2
// baseline (speedup 1.0000x reference)
#include <cuda_runtime.h>
#include <cuda_bf16.h>
#include <cstdint>

// ============================================================================
// Supervised contrastive loss, B=8192, D=256, NUM_CLASSES=100, T=0.07
//
// K0: label width detect (int64 vs int32) + convert + zero accumulators
// K1: z fp32 -> bf16
// K2: fused bf16 GEMM (z z^T / T) + exp + label-mask + row-sum -> sum_neg[i]
// K3: positive pairs in fp32: pair_loss = log1p(sum_neg_i * exp(-dot/T)),
//     row mean, accumulate loss sum + valid count
// K4: finalize scalar
// ============================================================================

#define B_N   8192
#define D_K   256
#define INV_T 14.285714285714285714f  // 1 / 0.07

// ---- scratch (static device memory; no allocations anywhere) ----
__device__ __nv_bfloat16 g_zb[B_N * D_K];   // 4 MB, bf16 copy of z
__device__ int           g_lab[B_N];
__device__ float         g_sumneg[B_N];
__device__ float         g_loss_sum;
__device__ int           g_valid;

// ============================================================================
// K0: prep
// ============================================================================
__global__ void k_prep(const void* lab_raw) {
    __shared__ int s_nonzero;
    int t = threadIdx.x;
    if (t == 0) s_nonzero = 0;
    __syncthreads();
    const int* p32 = (const int*)lab_raw;
    // If labels are int64 little-endian, every odd 32-bit word is 0 (labels in
    // [0,100)). If int32, 4096 random labels all being 0 is impossible.
    int local = 0;
    for (int i = t; i < B_N / 2; i += blockDim.x)
        if (p32[2 * i + 1] != 0) local = 1;
    if (local) atomicOr(&s_nonzero, 1);
    __syncthreads();
    bool is64 = (s_nonzero == 0);
    for (int i = t; i < B_N; i += blockDim.x) {
        g_lab[i]    = is64 ? p32[2 * i] : p32[i];
        g_sumneg[i] = 0.f;
    }
    if (t == 0) { g_loss_sum = 0.f; g_valid = 0; }
}

// ============================================================================
// K1: fp32 -> bf16
// ============================================================================
__global__ void k_cvt(const float* __restrict__ z) {
    int i = blockIdx.x * blockDim.x + threadIdx.x;
    if (i < B_N * D_K) g_zb[i] = __float2bfloat16(z[i]);
}

// ============================================================================
// K2: fused GEMM + exp + mask + row-sum
// ============================================================================
#define BM  128
#define BN  128
#define BK  32
#define LDT 40      // padded smem stride (elements): 80B rows, 16B-aligned,
                    // conflict-free for ldmatrix (row*20 words distinct mod 32)

__device__ __forceinline__ void cp16(uint32_t dst, const void* src) {
    asm volatile("cp.async.cg.shared.global [%0], [%1], 16;\n" :: "r"(dst), "l"(src));
}

__device__ __forceinline__ void mma16816(float* c, const uint32_t* a, const uint32_t* b) {
    asm volatile(
        "mma.sync.aligned.m16n8k16.row.col.f32.bf16.bf16.f32 "
        "{%0,%1,%2,%3}, {%4,%5,%6,%7}, {%8,%9}, {%0,%1,%2,%3};"
        : "+f"(c[0]), "+f"(c[1]), "+f"(c[2]), "+f"(c[3])
        : "r"(a[0]), "r"(a[1]), "r"(a[2]), "r"(a[3]), "r"(b[0]), "r"(b[1]));
}

__global__ __launch_bounds__(256, 2) void k_gemm() {
    __shared__ __align__(16) __nv_bfloat16 sA[2][BM * LDT];
    __shared__ __align__(16) __nv_bfloat16 sB[2][BN * LDT];
    __shared__ int   s_rlab[BM];
    __shared__ int   s_clab[BN];
    __shared__ float s_rows[BM];

    const int t    = threadIdx.x;
    const int warp = t >> 5;
    const int lane = t & 31;
    const int wm   = warp >> 2;   // 0..1  (64-row band)
    const int wn   = warp & 3;    // 0..3  (32-col band)

    const int iBase = blockIdx.y * BM;
    const int jBase = blockIdx.x * BN;

    if (t < BM) {
        s_rlab[t] = g_lab[iBase + t];
        s_clab[t] = g_lab[jBase + t];
        s_rows[t] = 0.f;
    }

    const __nv_bfloat16* gA = g_zb + (size_t)iBase * D_K;
    const __nv_bfloat16* gB = g_zb + (size_t)jBase * D_K;

    uint32_t aS[2], bS[2];
    aS[0] = (uint32_t)__cvta_generic_to_shared(&sA[0][0]);
    aS[1] = (uint32_t)__cvta_generic_to_shared(&sA[1][0]);
    bS[0] = (uint32_t)__cvta_generic_to_shared(&sB[0][0]);
    bS[1] = (uint32_t)__cvta_generic_to_shared(&sB[1][0]);

    float acc[4][4][4];
    #pragma unroll
    for (int a = 0; a < 4; a++)
        #pragma unroll
        for (int b = 0; b < 4; b++)
            #pragma unroll
            for (int r = 0; r < 4; r++) acc[a][b][r] = 0.f;

    // per-thread tile-copy coordinates: 512 x 16B chunks per tile, 2 per thread
    auto load_stage = [&](int st, int kt) {
        int k0 = kt * BK;
        #pragma unroll
        for (int rep = 0; rep < 2; rep++) {
            int c   = t + rep * 256;
            int row = c >> 2;
            int cc  = c & 3;
            uint32_t so = (uint32_t)(row * LDT + cc * 8) * 2u;
            size_t   go = (size_t)row * D_K + k0 + cc * 8;
            cp16(aS[st] + so, gA + go);
            cp16(bS[st] + so, gB + go);
        }
    };

    load_stage(0, 0);
    asm volatile("cp.async.commit_group;\n" ::);

    const int NKT = D_K / BK;   // 8
    for (int kt = 0; kt < NKT; kt++) {
        int cur = kt & 1;
        asm volatile("cp.async.wait_group 0;\n" ::);
        __syncthreads();
        if (kt + 1 < NKT) {
            load_stage((kt + 1) & 1, kt + 1);
            asm volatile("cp.async.commit_group;\n" ::);
        }

        #pragma unroll
        for (int ks = 0; ks < 2; ks++) {
            const int k0 = ks * 16;
            uint32_t af[4][4], bf[4][2];
            #pragma unroll
            for (int mi = 0; mi < 4; mi++) {
                int r = wm * 64 + mi * 16 + (lane & 15);
                int c = k0 + ((lane >> 4) << 3);
                uint32_t addr = aS[cur] + (uint32_t)(r * LDT + c) * 2u;
                asm volatile(
                    "ldmatrix.sync.aligned.m8n8.x4.shared.b16 {%0,%1,%2,%3}, [%4];"
                    : "=r"(af[mi][0]), "=r"(af[mi][1]), "=r"(af[mi][2]), "=r"(af[mi][3])
                    : "r"(addr));
            }
            #pragma unroll
            for (int ni = 0; ni < 4; ni++) {
                int l = lane & 15;
                int r = wn * 32 + ni * 8 + (l & 7);
                int c = k0 + ((l >> 3) << 3);
                uint32_t addr = bS[cur] + (uint32_t)(r * LDT + c) * 2u;
                asm volatile(
                    "ldmatrix.sync.aligned.m8n8.x2.shared.b16 {%0,%1}, [%2];"
                    : "=r"(bf[ni][0]), "=r"(bf[ni][1])
                    : "r"(addr));
            }
            #pragma unroll
            for (int mi = 0; mi < 4; mi++)
                #pragma unroll
                for (int ni = 0; ni < 4; ni++)
                    mma16816(acc[mi][ni], af[mi], bf[ni]);
        }
        __syncthreads();
    }

    // ---- epilogue: exp, label-mask, row-sum ----
    const int qrow = lane >> 2;        // 0..7
    const int qcol = (lane & 3) * 2;   // 0,2,4,6

    #pragma unroll
    for (int mi = 0; mi < 4; mi++) {
        int r0  = wm * 64 + mi * 16 + qrow;
        int lr0 = s_rlab[r0];
        int lr1 = s_rlab[r0 + 8];
        float s0 = 0.f, s1 = 0.f;
        #pragma unroll
        for (int ni = 0; ni < 4; ni++) {
            int c0  = wn * 32 + ni * 8 + qcol;
            int lc0 = s_clab[c0];
            int lc1 = s_clab[c0 + 1];
            if (lr0 != lc0) s0 += __expf(acc[mi][ni][0] * INV_T);
            if (lr0 != lc1) s0 += __expf(acc[mi][ni][1] * INV_T);
            if (lr1 != lc0) s1 += __expf(acc[mi][ni][2] * INV_T);
            if (lr1 != lc1) s1 += __expf(acc[mi][ni][3] * INV_T);
        }
        s0 += __shfl_xor_sync(0xffffffffu, s0, 1);
        s0 += __shfl_xor_sync(0xffffffffu, s0, 2);
        s1 += __shfl_xor_sync(0xffffffffu, s1, 1);
        s1 += __shfl_xor_sync(0xffffffffu, s1, 2);
        if ((lane & 3) == 0) {
            atomicAdd(&s_rows[r0],     s0);
            atomicAdd(&s_rows[r0 + 8], s1);
        }
    }
    __syncthreads();
    if (t < BM) atomicAdd(&g_sumneg[iBase + t], s_rows[t]);
}

// ============================================================================
// K3: positive pairs in fp32
// ============================================================================
__global__ __launch_bounds__(256) void k_pos(const float* __restrict__ z) {
    __shared__ float s_zi[D_K];
    __shared__ float s_pl[8];
    __shared__ int   s_cnt[8];

    const int i    = blockIdx.x;
    const int t    = threadIdx.x;
    const int warp = t >> 5;
    const int lane = t & 31;

    s_zi[t] = z[(size_t)i * D_K + t];
    __syncthreads();

    const int   li = g_lab[i];
    const float sn = g_sumneg[i];

    float plsum = 0.f;
    int   cnt   = 0;

    // each warp scans a contiguous 1024-row slab; matches processed whole-warp
    for (int base = warp * 1024; base < warp * 1024 + 1024; base += 32) {
        int  j = base + lane;
        bool m = (g_lab[j] == li) && (j != i);
        unsigned mask = __ballot_sync(0xffffffffu, m);
        while (mask) {
            int b = __ffs(mask) - 1;
            mask &= mask - 1;
            int jj = base + b;
            const float* zj = z + (size_t)jj * D_K;
            float p = 0.f;
            #pragma unroll
            for (int e = 0; e < 8; e++) {
                int idx = lane + e * 32;
                p += s_zi[idx] * zj[idx];
            }
            #pragma unroll
            for (int off = 16; off; off >>= 1)
                p += __shfl_xor_sync(0xffffffffu, p, off);
            if (lane == 0) {
                plsum += log1pf(sn * __expf(-p * INV_T));
                cnt++;
            }
        }
    }

    if (lane == 0) { s_pl[warp] = plsum; s_cnt[warp] = cnt; }
    __syncthreads();
    if (t == 0) {
        float tp = 0.f; int tc = 0;
        #pragma unroll
        for (int w = 0; w < 8; w++) { tp += s_pl[w]; tc += s_cnt[w]; }
        if (tc > 0) {
            atomicAdd(&g_loss_sum, tp / (float)tc);
            atomicAdd(&g_valid, 1);
        }
    }
}

// ============================================================================
// K4: finalize
// ============================================================================
__global__ void k_fin(float* out) {
    out[0] = (g_valid > 0) ? g_loss_sum / (float)g_valid : 0.f;
}

// ============================================================================
// launch
// ============================================================================
extern "C" void kernel_launch(void* const* d_in, const int* in_sizes, int n_in,
                              void* d_out, int out_size) {
    const float* z   = (const float*)d_in[0];
    const void*  lab = d_in[1];

    k_prep<<<1, 1024>>>(lab);
    k_cvt<<<(B_N * D_K + 255) / 256, 256>>>(z);
    dim3 grid(B_N / BN, B_N / BM);
    k_gemm<<<grid, 256>>>();
    k_pos<<<B_N, 256>>>(z);
    k_fin<<<1, 1>>>((float*)d_out);
}